// round 13
// baseline (speedup 1.0000x reference)
#include <cuda_runtime.h>
#include <cstdint>

// knnLoss:  loss = sum_{b,t} min_s ||s-t||^2 / 120000  (exact).
// memset -> pack (sources binned per cell, targets per 2x2x2 supercell)
//        -> search: ONE WARP per (supercell, 32-target chunk). Lanes hold 32
//           targets of the same supercell; the warp walks the supercell+-1
//           cell union reading points with warp-UNIFORM gmem loads (L1
//           broadcast). Exact bound: any source in an unscanned cell is >= h
//           away (holds under index clamping); best <= 0.9995 h^2 proves the
//           min, else warp-cooperative brute scan over all NPTS sources.

#define OUT_HW   100
#define STRIDE   4
#define NPTS     10000
#define NB       4
#define NBNPTS   (NB * NPTS)
#define HW       400
#define PLANE    (HW * HW)
#define NALL     (2 * NBNPTS)
#define G        16
#define G3       (G * G * G)
#define GS       8
#define NSCB     (GS * GS * GS)       // 512
#define NSC      (NB * NSCB)          // 2048
#define NSEG     (NB * G3)            // 16384
#define CAP      96
#define SC_CAP   512
#define MAXC     (SC_CAP / 32)        // 16 chunks per supercell
#define NUNITS   (NSC * MAXC)         // 32768
#define RANGE    3.2f
#define HCELL    0.4f
#define INVH     2.5f
#define HBOUND   (0.9995f * HCELL * HCELL)
#define FINF     3.4e38f
#define NOVF_MAX 2048

#define SBLK     2048                 // search blocks
#define STHR     128                  // 4 warps -> 8192 warps, 4 units each

// zero region layout
#define ZSRC   0
#define ZTGT   NSEG
#define ZOVF   (NSEG + NSC)
#define ZFBT   (NSEG + NSC + 1)
#define ZDONE  (NSEG + NSC + 2)
#define ZN     (NSEG + NSC + 3)

__device__ int    g_zero[ZN];
__device__ float4 g_bins[NSEG * CAP];       // source cell bins
__device__ float4 g_tbins[NSC * SC_CAP];    // target supercell bins
__device__ float4 g_sflat[NBNPTS];          // flat sources (fallback scans)
__device__ float4 g_ovf[NOVF_MAX];          // source cell overflow
__device__ int    g_ovfb[NOVF_MAX];
__device__ float4 g_fbt[NOVF_MAX];          // target supercell overflow
__device__ int    g_fbtb[NOVF_MAX];
__device__ float  g_bpart[SBLK];

// ---------------------------------------------------------------------------
__global__ void __launch_bounds__(256)
pack_kernel(const float* __restrict__ tgt, const float* __restrict__ src) {
    int i = blockIdx.x * blockDim.x + threadIdx.x;
    if (i >= NALL) return;
    int which = i / NBNPTS;               // 0 = source, 1 = target
    int r = i - which * NBNPTS;
    int b = r / NPTS;
    int m = r - b * NPTS;
    int h = (m / OUT_HW) * STRIDE;
    int w = (m - (m / OUT_HW) * OUT_HW) * STRIDE;
    const float* p = (which == 0 ? src : tgt) + (size_t)b * 3 * PLANE + h * HW + w;
    float x = p[0];
    float y = p[PLANE];
    float z = p[2 * PLANE];
    float4 v = make_float4(x, y, z, fmaf(x, x, fmaf(y, y, z * z)));

    int cx = min(max((int)floorf((x + RANGE) * INVH), 0), G - 1);
    int cy = min(max((int)floorf((y + RANGE) * INVH), 0), G - 1);
    int cz = min(max((int)floorf((z + RANGE) * INVH), 0), G - 1);

    if (which == 0) {
        g_sflat[r] = v;
        int cell = b * G3 + (cz * G + cy) * G + cx;
        int rank = atomicAdd(&g_zero[ZSRC + cell], 1);
        if (rank < CAP) {
            g_bins[cell * CAP + rank] = v;
        } else {
            int o = atomicAdd(&g_zero[ZOVF], 1);
            if (o < NOVF_MAX) { g_ovf[o] = v; g_ovfb[o] = b; }
        }
    } else {
        int sc = b * NSCB + ((cz >> 1) * GS + (cy >> 1)) * GS + (cx >> 1);
        int rank = atomicAdd(&g_zero[ZTGT + sc], 1);
        if (rank < SC_CAP) {
            g_tbins[sc * SC_CAP + rank] = v;
        } else {
            int o = atomicAdd(&g_zero[ZFBT], 1);
            if (o < NOVF_MAX) { g_fbt[o] = v; g_fbtb[o] = b; }
        }
    }
}

// ---------------------------------------------------------------------------
// One warp per (supercell, chunk) unit. Units enumerated c*NSC+sc so that
// low unit ids are the populated ones; each warp handles 4 strided units.
// ---------------------------------------------------------------------------
__global__ void __launch_bounds__(STHR)
search_kernel(float* __restrict__ out) {
    __shared__ float red[STHR];
    __shared__ int   slast;

    int tid  = threadIdx.x;
    int wid  = tid >> 5;
    int lane = tid & 31;
    int gw   = blockIdx.x * 4 + wid;      // 0..8191

    float lsum = 0.0f;

    #pragma unroll 1
    for (int k = 0; k < 4; k++) {
        int unit = gw + k * 8192;
        int c  = unit >> 11;              // unit / NSC
        int sc = unit & (NSC - 1);
        int ntgt = min(g_zero[ZTGT + sc], SC_CAP);
        if (ntgt <= 32 * c) continue;

        int b   = sc >> 9;
        int s   = sc & (NSCB - 1);
        int scx = s & 7, scy = (s >> 3) & 7, scz = s >> 6;
        int segbase = b * G3;

        int ti = 32 * c + lane;
        bool act = ti < ntgt;
        float4 tv = g_tbins[sc * SC_CAP + (act ? ti : 0)];
        float ax = -2.0f * tv.x, ay = -2.0f * tv.y, az = -2.0f * tv.z;

        int x0 = max(2 * scx - 1, 0), x1 = min(2 * scx + 2, G - 1);
        int y0 = max(2 * scy - 1, 0), y1 = min(2 * scy + 2, G - 1);
        int z0 = max(2 * scz - 1, 0), z1 = min(2 * scz + 2, G - 1);

        float b0 = FINF, b1 = FINF;
        for (int cz = z0; cz <= z1; cz++) {
            for (int cy = y0; cy <= y1; cy++) {
                int rowc = segbase + (cz * G + cy) * G;
                // fixed 4-wide x walk, predicated counts (MLP on count loads)
                int n0 = (x0 + 0 <= x1) ? min(g_zero[ZSRC + rowc + x0 + 0], CAP) : 0;
                int n1 = (x0 + 1 <= x1) ? min(g_zero[ZSRC + rowc + x0 + 1], CAP) : 0;
                int n2 = (x0 + 2 <= x1) ? min(g_zero[ZSRC + rowc + x0 + 2], CAP) : 0;
                int n3 = (x0 + 3 <= x1) ? min(g_zero[ZSRC + rowc + x0 + 3], CAP) : 0;
                #pragma unroll
                for (int q = 0; q < 4; q++) {
                    int n = (q == 0) ? n0 : (q == 1) ? n1 : (q == 2) ? n2 : n3;
                    const float4* bp = g_bins + (size_t)(rowc + x0 + q) * CAP;
                    int p = 0;
                    for (; p + 2 <= n; p += 2) {
                        float4 s0 = bp[p];
                        float4 s1 = bp[p + 1];
                        float d0 = fmaf(s0.x, ax, fmaf(s0.y, ay, fmaf(s0.z, az, s0.w)));
                        float d1 = fmaf(s1.x, ax, fmaf(s1.y, ay, fmaf(s1.z, az, s1.w)));
                        b0 = fminf(b0, d0);
                        b1 = fminf(b1, d1);
                    }
                    if (p < n) {
                        float4 s0 = bp[p];
                        b0 = fminf(b0,
                            fmaf(s0.x, ax, fmaf(s0.y, ay, fmaf(s0.z, az, s0.w))));
                    }
                }
            }
        }
        float best = fminf(b0, b1);

        // source-overflow points (normally zero)
        int novf = min(g_zero[ZOVF], NOVF_MAX);
        for (int o = 0; o < novf; o++) {
            if (g_ovfb[o] == b) {
                float4 s0 = g_ovf[o];
                best = fminf(best,
                    fmaf(s0.x, ax, fmaf(s0.y, ay, fmaf(s0.z, az, s0.w))));
            }
        }
        float full = best + tv.w;

        // bound unproven -> warp-cooperative exact brute scan of whole batch
        unsigned need = __ballot_sync(0xffffffffu, act && (full > HBOUND));
        while (need) {
            int sl = __ffs(need) - 1;
            need &= need - 1;
            float bx = __shfl_sync(0xffffffffu, ax, sl);
            float by = __shfl_sync(0xffffffffu, ay, sl);
            float bz = __shfl_sync(0xffffffffu, az, sl);
            const float4* sp = g_sflat + b * NPTS;
            float m0 = FINF, m1 = FINF;
            for (int p = lane; p < NPTS; p += 64) {
                float4 s0 = sp[p];
                m0 = fminf(m0, fmaf(s0.x, bx, fmaf(s0.y, by, fmaf(s0.z, bz, s0.w))));
                if (p + 32 < NPTS) {
                    float4 s1 = sp[p + 32];
                    m1 = fminf(m1, fmaf(s1.x, bx, fmaf(s1.y, by, fmaf(s1.z, bz, s1.w))));
                }
            }
            float mb = fminf(m0, m1);
            #pragma unroll
            for (int o = 16; o > 0; o >>= 1)
                mb = fminf(mb, __shfl_xor_sync(0xffffffffu, mb, o));
            float tw = __shfl_sync(0xffffffffu, tv.w, sl);
            if (lane == sl) full = mb + tw;
        }
        if (act) lsum += full;
    }

    // block 0: overflowed targets (normally none) -> warp brute per entry
    if (blockIdx.x == 0) {
        int nfbt = min(g_zero[ZFBT], NOVF_MAX);
        for (int e = wid; e < nfbt; e += 4) {
            float4 tv = g_fbt[e];
            int bb = g_fbtb[e];
            float bx = -2.0f * tv.x, by = -2.0f * tv.y, bz = -2.0f * tv.z;
            const float4* sp = g_sflat + bb * NPTS;
            float mb = FINF;
            for (int p = lane; p < NPTS; p += 32) {
                float4 s0 = sp[p];
                mb = fminf(mb, fmaf(s0.x, bx, fmaf(s0.y, by, fmaf(s0.z, bz, s0.w))));
            }
            #pragma unroll
            for (int o = 16; o > 0; o >>= 1)
                mb = fminf(mb, __shfl_xor_sync(0xffffffffu, mb, o));
            if (lane == 0) lsum += mb + tv.w;
        }
    }

    // block reduce -> fixed-order final reduce in last-arriving block
    red[tid] = lsum;
    __syncthreads();
    #pragma unroll
    for (int st = STHR / 2; st > 0; st >>= 1) {
        if (tid < st) red[tid] += red[tid + st];
        __syncthreads();
    }
    if (tid == 0) {
        g_bpart[blockIdx.x] = red[0];
        __threadfence();
        slast = (atomicAdd(&g_zero[ZDONE], 1) == SBLK - 1);
    }
    __syncthreads();

    if (slast) {
        float ssum = 0.0f;
        for (int i = tid; i < SBLK; i += STHR) ssum += g_bpart[i];
        red[tid] = ssum;
        __syncthreads();
        #pragma unroll
        for (int st = STHR / 2; st > 0; st >>= 1) {
            if (tid < st) red[tid] += red[tid + st];
            __syncthreads();
        }
        if (tid == 0)
            out[0] = red[0] * (1.0f / (float)(NBNPTS * 3));
    }
}

// ---------------------------------------------------------------------------
extern "C" void kernel_launch(void* const* d_in, const int* in_sizes, int n_in,
                              void* d_out, int out_size) {
    const float* tgt = (const float*)d_in[0];   // target_pc (4,3,400,400)
    const float* src = (const float*)d_in[1];   // source_pc (4,3,400,400)
    float* out = (float*)d_out;

    void* zaddr = nullptr;
    cudaGetSymbolAddress(&zaddr, g_zero);
    cudaMemsetAsync(zaddr, 0, ZN * sizeof(int));

    pack_kernel<<<(NALL + 255) / 256, 256>>>(tgt, src);
    search_kernel<<<SBLK, STHR>>>(out);
}

// round 16
// speedup vs baseline: 2.0585x; 2.0585x over previous
#include <cuda_runtime.h>
#include <cstdint>

// knnLoss brute-force v3:
//   loss = sum_{b,t} [ ||t||^2 + min_s (||s||^2 - 2 t.s) ] / 120000
// f32x2 packed FMA (2 source pts / instr), SoA smem source tiles (broadcast
// LDS), 4 targets per thread (8 independent fma chains per body -> latency
// hidden), single-wave 800-block grid.

#define OUT_HW   100
#define STRIDE   4
#define NPTS     10000
#define NB       4
#define HW       400
#define PLANE    (HW * HW)
#define SSPLIT   10
#define SCHUNK   (NPTS / SSPLIT)      // 1000 (divisible by 8)
#define NTHREADS 128
#define TGT      4
#define TPB      (NTHREADS * TGT)     // 512 targets per block
#define NTCHUNK  ((NPTS + TPB - 1) / TPB)  // 20

__device__ float4 g_t[NB * NPTS];
__device__ float  g_sx[NB * NPTS];
__device__ float  g_sy[NB * NPTS];
__device__ float  g_sz[NB * NPTS];
__device__ float  g_sw[NB * NPTS];
__device__ float  g_partial[SSPLIT][NB * NPTS];

typedef unsigned long long ull;

__device__ __forceinline__ ull fma2(ull a, ull b, ull c) {
    ull d;
    asm("fma.rn.f32x2 %0, %1, %2, %3;" : "=l"(d) : "l"(a), "l"(b), "l"(c));
    return d;
}
__device__ __forceinline__ ull dup2(float v) {
    ull r;
    asm("mov.b64 %0, {%1, %1};" : "=l"(r) : "f"(v));
    return r;
}
__device__ __forceinline__ void unpack2(ull v, float& lo, float& hi) {
    asm("mov.b64 {%0, %1}, %2;" : "=f"(lo), "=f"(hi) : "l"(v));
}
__device__ __forceinline__ void lds_x4(const float* p, ull& a, ull& b) {
    uint32_t addr = (uint32_t)__cvta_generic_to_shared(p);
    asm volatile("ld.shared.v2.b64 {%0, %1}, [%2];"
                 : "=l"(a), "=l"(b) : "r"(addr));
}

// ---------------------------------------------------------------------------
// Kernel 1: downsample + pack. Targets -> AoS float4 (x,y,z,|t|^2);
// sources -> SoA for packed broadcast smem loads.
// ---------------------------------------------------------------------------
__global__ void pack_kernel(const float* __restrict__ tgt,
                            const float* __restrict__ src) {
    int i = blockIdx.x * blockDim.x + threadIdx.x;
    if (i >= 2 * NB * NPTS) return;
    int which = i / (NB * NPTS);
    int r = i - which * (NB * NPTS);
    int b = r / NPTS;
    int m = r - b * NPTS;
    int h = (m / OUT_HW) * STRIDE;
    int w = (m - (m / OUT_HW) * OUT_HW) * STRIDE;
    const float* p = (which == 0 ? tgt : src) + (size_t)b * 3 * PLANE + h * HW + w;
    float x = p[0];
    float y = p[PLANE];
    float z = p[2 * PLANE];
    float nrm = fmaf(x, x, fmaf(y, y, z * z));
    if (which == 0) {
        g_t[r] = make_float4(x, y, z, nrm);
    } else {
        g_sx[r] = x; g_sy[r] = y; g_sz[r] = z; g_sw[r] = nrm;
    }
}

// ---------------------------------------------------------------------------
// Kernel 2: grid (20, 4, 10) = 800 blocks x 128 threads, 4 targets/thread.
// ---------------------------------------------------------------------------
__global__ void __launch_bounds__(NTHREADS)
min_kernel() {
    __shared__ alignas(16) float sx[SCHUNK];
    __shared__ alignas(16) float sy[SCHUNK];
    __shared__ alignas(16) float sz[SCHUNK];
    __shared__ alignas(16) float sw[SCHUNK];

    int b  = blockIdx.y;
    int sc = blockIdx.z;
    int sbase = b * NPTS + sc * SCHUNK;

    for (int j = threadIdx.x; j < SCHUNK; j += NTHREADS) {
        sx[j] = g_sx[sbase + j];
        sy[j] = g_sy[sbase + j];
        sz[j] = g_sz[sbase + j];
        sw[j] = g_sw[sbase + j];
    }
    __syncthreads();

    int tb = blockIdx.x * TPB + threadIdx.x;
    int t0 = tb;
    int t1 = tb + NTHREADS;
    int t2 = tb + 2 * NTHREADS;
    int t3 = tb + 3 * NTHREADS;
    float4 tv0 = g_t[b * NPTS + (t0 < NPTS ? t0 : NPTS - 1)];
    float4 tv1 = g_t[b * NPTS + (t1 < NPTS ? t1 : NPTS - 1)];
    float4 tv2 = g_t[b * NPTS + (t2 < NPTS ? t2 : NPTS - 1)];
    float4 tv3 = g_t[b * NPTS + (t3 < NPTS ? t3 : NPTS - 1)];

    ull ax0 = dup2(-2.0f * tv0.x), ay0 = dup2(-2.0f * tv0.y), az0 = dup2(-2.0f * tv0.z);
    ull ax1 = dup2(-2.0f * tv1.x), ay1 = dup2(-2.0f * tv1.y), az1 = dup2(-2.0f * tv1.z);
    ull ax2 = dup2(-2.0f * tv2.x), ay2 = dup2(-2.0f * tv2.y), az2 = dup2(-2.0f * tv2.z);
    ull ax3 = dup2(-2.0f * tv3.x), ay3 = dup2(-2.0f * tv3.y), az3 = dup2(-2.0f * tv3.z);

    const float INF = 3.4e38f;
    float a00 = INF, a01 = INF;     // target 0 accumulators
    float a10 = INF, a11 = INF;     // target 1
    float a20 = INF, a21 = INF;     // target 2
    float a30 = INF, a31 = INF;     // target 3

    #pragma unroll 2
    for (int j = 0; j < SCHUNK; j += 4) {
        ull x01, x23, y01, y23, z01, z23, w01, w23;
        lds_x4(&sx[j], x01, x23);
        lds_x4(&sy[j], y01, y23);
        lds_x4(&sz[j], z01, z23);
        lds_x4(&sw[j], w01, w23);

        ull d; float lo, hi;

        d = fma2(z01, az0, fma2(y01, ay0, fma2(x01, ax0, w01)));
        unpack2(d, lo, hi); a00 = fminf(a00, lo); a01 = fminf(a01, hi);
        d = fma2(z01, az1, fma2(y01, ay1, fma2(x01, ax1, w01)));
        unpack2(d, lo, hi); a10 = fminf(a10, lo); a11 = fminf(a11, hi);
        d = fma2(z01, az2, fma2(y01, ay2, fma2(x01, ax2, w01)));
        unpack2(d, lo, hi); a20 = fminf(a20, lo); a21 = fminf(a21, hi);
        d = fma2(z01, az3, fma2(y01, ay3, fma2(x01, ax3, w01)));
        unpack2(d, lo, hi); a30 = fminf(a30, lo); a31 = fminf(a31, hi);

        d = fma2(z23, az0, fma2(y23, ay0, fma2(x23, ax0, w23)));
        unpack2(d, lo, hi); a00 = fminf(a00, lo); a01 = fminf(a01, hi);
        d = fma2(z23, az1, fma2(y23, ay1, fma2(x23, ax1, w23)));
        unpack2(d, lo, hi); a10 = fminf(a10, lo); a11 = fminf(a11, hi);
        d = fma2(z23, az2, fma2(y23, ay2, fma2(x23, ax2, w23)));
        unpack2(d, lo, hi); a20 = fminf(a20, lo); a21 = fminf(a21, hi);
        d = fma2(z23, az3, fma2(y23, ay3, fma2(x23, ax3, w23)));
        unpack2(d, lo, hi); a30 = fminf(a30, lo); a31 = fminf(a31, hi);
    }

    float* dst = &g_partial[sc][b * NPTS];
    if (t0 < NPTS) dst[t0] = fminf(a00, a01);
    if (t1 < NPTS) dst[t1] = fminf(a10, a11);
    if (t2 < NPTS) dst[t2] = fminf(a20, a21);
    if (t3 < NPTS) dst[t3] = fminf(a30, a31);
}

// ---------------------------------------------------------------------------
// Kernel 3: combine s-split partials, add |t|^2, deterministic reduce.
// ---------------------------------------------------------------------------
__global__ void __launch_bounds__(1024)
reduce_kernel(float* __restrict__ out) {
    __shared__ float red[1024];
    float sum = 0.0f;
    for (int i = threadIdx.x; i < NB * NPTS; i += 1024) {
        float m = g_partial[0][i];
        #pragma unroll
        for (int s = 1; s < SSPLIT; s++)
            m = fminf(m, g_partial[s][i]);
        sum += m + g_t[i].w;
    }
    red[threadIdx.x] = sum;
    __syncthreads();
    #pragma unroll
    for (int s = 512; s > 0; s >>= 1) {
        if (threadIdx.x < s) red[threadIdx.x] += red[threadIdx.x + s];
        __syncthreads();
    }
    if (threadIdx.x == 0)
        out[0] = red[0] * (1.0f / (float)(NB * NPTS * 3));
}

// ---------------------------------------------------------------------------
extern "C" void kernel_launch(void* const* d_in, const int* in_sizes, int n_in,
                              void* d_out, int out_size) {
    const float* tgt = (const float*)d_in[0];   // target_pc (4,3,400,400)
    const float* src = (const float*)d_in[1];   // source_pc (4,3,400,400)
    float* out = (float*)d_out;

    int pack_total = 2 * NB * NPTS;
    pack_kernel<<<(pack_total + 255) / 256, 256>>>(tgt, src);

    dim3 grid(NTCHUNK, NB, SSPLIT);
    min_kernel<<<grid, NTHREADS>>>();

    reduce_kernel<<<1, 1024>>>(out);
}